// round 3
// baseline (speedup 1.0000x reference)
#include <cuda_runtime.h>
#include <cstdint>
#include <math.h>

constexpr int T = 512;
constexpr int N = 1024;
constexpr int D = 256;
constexpr int E = 256;          // output dim of fc (== D)
constexpr int M_ROWS = T * N;   // 524288

// -------- scratch: scores e[t,n] --------
__device__ float g_e[M_ROWS];

// ---------------- K1: fused score GEMM ----------------
// Tile: CTA = 128 rows x 256 e, K staged in chunks of 64.
// 8 warps: warp_r = wid>>2 (row half of 64), warp_c = wid&3 (e quarter of 64).
// Per warp: 4 m-tiles (16 rows) x 8 n-tiles (8 e), mma.sync m16n8k8 tf32.

constexpr int BM = 128;
constexpr int BK = 64;
constexpr int LDA = 68;   // padded stride (words) -> conflict-free frags
constexpr int SMEM_FLOATS = BM * LDA + E * LDA + 256 + 256 + 128;
constexpr int SMEM_BYTES = SMEM_FLOATS * 4;

__device__ __forceinline__ uint32_t to_tf32(float x) {
    uint32_t r;
    asm("cvt.rna.tf32.f32 %0, %1;" : "=r"(r) : "f"(x));
    return r;
}

__device__ __forceinline__ void mma_tf32(float c[4], const uint32_t a[4],
                                         uint32_t b0, uint32_t b1) {
    asm volatile(
        "mma.sync.aligned.m16n8k8.row.col.f32.tf32.tf32.f32 "
        "{%0,%1,%2,%3}, {%4,%5,%6,%7}, {%8,%9}, {%0,%1,%2,%3};\n"
        : "+f"(c[0]), "+f"(c[1]), "+f"(c[2]), "+f"(c[3])
        : "r"(a[0]), "r"(a[1]), "r"(a[2]), "r"(a[3]), "r"(b0), "r"(b1));
}

__global__ __launch_bounds__(256, 1)
void score_kernel(const float* __restrict__ H, const float* __restrict__ fc_w,
                  const float* __restrict__ fc_b, const float* __restrict__ score_w) {
    extern __shared__ float smem[];
    uint32_t* A_sh = reinterpret_cast<uint32_t*>(smem);            // 128 x LDA
    uint32_t* B_sh = reinterpret_cast<uint32_t*>(smem + BM * LDA); // 256 x LDA
    float* fb_sh = smem + BM * LDA + E * LDA;   // 256
    float* sw_sh = fb_sh + 256;                 // 256
    float* esum  = sw_sh + 256;                 // 128

    const int tid  = threadIdx.x;
    const int wid  = tid >> 5;
    const int lane = tid & 31;
    const int g    = lane >> 2;   // groupID (row within frag)
    const int t4   = lane & 3;
    const int wr0  = (wid >> 2) * 64;  // warp row base within CTA
    const int we0  = (wid & 3) * 64;   // warp e base

    const int m0 = blockIdx.x * BM;

    if (tid < 256) { fb_sh[tid] = fc_b[tid]; sw_sh[tid] = score_w[tid]; }
    if (tid < 128) esum[tid] = 0.0f;

    float c[4][8][4];
#pragma unroll
    for (int mt = 0; mt < 4; ++mt)
#pragma unroll
        for (int nt = 0; nt < 8; ++nt)
#pragma unroll
            for (int i = 0; i < 4; ++i) c[mt][nt][i] = 0.0f;

    for (int kc = 0; kc < D / BK; ++kc) {
        // stage A chunk: 128 rows x 64 k
        const float* Ag = H + (size_t)m0 * D + kc * BK;
#pragma unroll
        for (int i = 0; i < 8; ++i) {
            int idx = tid + i * 256;
            int row = idx >> 4;
            int c4  = (idx & 15) * 4;
            float4 v = *reinterpret_cast<const float4*>(Ag + (size_t)row * D + c4);
            A_sh[row * LDA + c4 + 0] = to_tf32(v.x);
            A_sh[row * LDA + c4 + 1] = to_tf32(v.y);
            A_sh[row * LDA + c4 + 2] = to_tf32(v.z);
            A_sh[row * LDA + c4 + 3] = to_tf32(v.w);
        }
        // stage B chunk: 256 e x 64 k
        const float* Bg = fc_w + kc * BK;
#pragma unroll
        for (int i = 0; i < 16; ++i) {
            int idx = tid + i * 256;
            int e  = idx >> 4;
            int c4 = (idx & 15) * 4;
            float4 v = *reinterpret_cast<const float4*>(Bg + (size_t)e * D + c4);
            B_sh[e * LDA + c4 + 0] = to_tf32(v.x);
            B_sh[e * LDA + c4 + 1] = to_tf32(v.y);
            B_sh[e * LDA + c4 + 2] = to_tf32(v.z);
            B_sh[e * LDA + c4 + 3] = to_tf32(v.w);
        }
        __syncthreads();

#pragma unroll
        for (int kk = 0; kk < BK / 8; ++kk) {
            const int kb = kk * 8;
            uint32_t a[4][4];
#pragma unroll
            for (int mt = 0; mt < 4; ++mt) {
                int rb = wr0 + mt * 16;
                a[mt][0] = A_sh[(rb + g)     * LDA + kb + t4];
                a[mt][1] = A_sh[(rb + g + 8) * LDA + kb + t4];
                a[mt][2] = A_sh[(rb + g)     * LDA + kb + t4 + 4];
                a[mt][3] = A_sh[(rb + g + 8) * LDA + kb + t4 + 4];
            }
#pragma unroll
            for (int nt = 0; nt < 8; ++nt) {
                int eb = we0 + nt * 8;
                uint32_t b0 = B_sh[(eb + g) * LDA + kb + t4];
                uint32_t b1 = B_sh[(eb + g) * LDA + kb + t4 + 4];
#pragma unroll
                for (int mt = 0; mt < 4; ++mt) mma_tf32(c[mt][nt], a[mt], b0, b1);
            }
        }
        __syncthreads();
    }

    // epilogue: e_row = sum_e tanh(c + fc_b[e]) * score_w[e]
#pragma unroll
    for (int mt = 0; mt < 4; ++mt) {
        float sum0 = 0.0f, sum1 = 0.0f;
#pragma unroll
        for (int nt = 0; nt < 8; ++nt) {
            int e0 = we0 + nt * 8 + t4 * 2;
            int e1 = e0 + 1;
            float b0 = fb_sh[e0], b1 = fb_sh[e1];
            float s0 = sw_sh[e0], s1 = sw_sh[e1];
            sum0 += tanhf(c[mt][nt][0] + b0) * s0 + tanhf(c[mt][nt][1] + b1) * s1;
            sum1 += tanhf(c[mt][nt][2] + b0) * s0 + tanhf(c[mt][nt][3] + b1) * s1;
        }
        // reduce across the 4 lanes (t4) that share a row
        sum0 += __shfl_xor_sync(0xffffffffu, sum0, 1);
        sum0 += __shfl_xor_sync(0xffffffffu, sum0, 2);
        sum1 += __shfl_xor_sync(0xffffffffu, sum1, 1);
        sum1 += __shfl_xor_sync(0xffffffffu, sum1, 2);
        if (t4 == 0) {
            atomicAdd(&esum[wr0 + mt * 16 + g],     sum0);
            atomicAdd(&esum[wr0 + mt * 16 + g + 8], sum1);
        }
    }
    __syncthreads();
    if (tid < 128) g_e[m0 + tid] = esum[tid];
}

// ---------------- K2: causal softmax prefix scan ----------------
// One block per channel n (64 threads, float4 over D=256).
// Global max per n, then cumulative p*H / cumulative p.

__global__ __launch_bounds__(64)
void scan_kernel(const float* __restrict__ H, float* __restrict__ C) {
    const int n   = blockIdx.x;
    const int tid = threadIdx.x;
    __shared__ float red[64];

    // phase A: M = max_t e[t,n]
    float mx = -INFINITY;
#pragma unroll
    for (int j = 0; j < 8; ++j) mx = fmaxf(mx, g_e[(size_t)(tid * 8 + j) * N + n]);
    red[tid] = mx;
    __syncthreads();
    for (int s = 32; s > 0; s >>= 1) {
        if (tid < s) red[tid] = fmaxf(red[tid], red[tid + s]);
        __syncthreads();
    }
    const float Mn = red[0];

    // phase B: prefix scan over t
    const float* Hp = H + (size_t)n * D + tid * 4;
    float*       Cp = C + (size_t)n * D + tid * 4;
    const float* ep = g_e + n;

    float nx = 0.f, ny = 0.f, nz = 0.f, nw = 0.f;
    float den = 0.f;
#pragma unroll 4
    for (int t = 0; t < T; ++t) {
        const size_t off = (size_t)t * N * D;
        float p = __expf(ep[(size_t)t * N] - Mn);
        float4 h = *reinterpret_cast<const float4*>(Hp + off);
        den += p;
        nx = fmaf(p, h.x, nx);
        ny = fmaf(p, h.y, ny);
        nz = fmaf(p, h.z, nz);
        nw = fmaf(p, h.w, nw);
        float inv = __fdividef(1.0f, den);
        float4 o;
        o.x = nx * inv; o.y = ny * inv; o.z = nz * inv; o.w = nw * inv;
        *reinterpret_cast<float4*>(Cp + off) = o;
    }
}

// ---------------- launch ----------------
extern "C" void kernel_launch(void* const* d_in, const int* in_sizes, int n_in,
                              void* d_out, int out_size) {
    const float* H       = (const float*)d_in[0];
    const float* fc_w    = (const float*)d_in[1];
    const float* fc_b    = (const float*)d_in[2];
    const float* score_w = (const float*)d_in[3];
    float* C = (float*)d_out;

    cudaFuncSetAttribute(score_kernel, cudaFuncAttributeMaxDynamicSharedMemorySize, SMEM_BYTES);
    score_kernel<<<M_ROWS / BM, 256, SMEM_BYTES>>>(H, fc_w, fc_b, score_w);
    scan_kernel<<<N, 64>>>(H, C);
}

// round 8
// speedup vs baseline: 1.7279x; 1.7279x over previous
#include <cuda_runtime.h>
#include <cuda_fp16.h>
#include <cstdint>
#include <math.h>

constexpr int T = 512;
constexpr int N = 1024;
constexpr int D = 256;
constexpr int M_ROWS = T * N;   // 524288

// scratch: scores e[t,n]
__device__ float g_e[M_ROWS];

// ======================= helpers =======================
__device__ __forceinline__ uint32_t smem_u32(const void* p) {
    uint32_t a;
    asm("{ .reg .u64 t; cvta.to.shared.u64 t, %1; cvt.u32.u64 %0, t; }"
        : "=r"(a) : "l"(p));
    return a;
}
__device__ __forceinline__ uint32_t sw128(uint32_t b) { return b ^ ((b >> 3) & 0x70); }

__device__ __forceinline__ void mbar_init(uint32_t a, uint32_t cnt) {
    asm volatile("mbarrier.init.shared.b64 [%0], %1;" :: "r"(a), "r"(cnt) : "memory");
}
__device__ __forceinline__ void mbar_arrive(uint32_t a) {
    asm volatile("mbarrier.arrive.shared.b64 _, [%0];" :: "r"(a) : "memory");
}
__device__ __forceinline__ void mbar_wait(uint32_t a, uint32_t parity) {
    asm volatile(
        "{\n\t.reg .pred P;\n"
        "W_%=:\n\t"
        "mbarrier.try_wait.parity.acquire.cta.shared::cta.b64 P, [%0], %1, 0x989680;\n\t"
        "@P bra.uni DN_%=;\n\t"
        "bra.uni W_%=;\n"
        "DN_%=:\n\t}"
        :: "r"(a), "r"(parity) : "memory");
}
__device__ __forceinline__ void sts128(uint32_t addr, uint32_t x, uint32_t y,
                                       uint32_t z, uint32_t w) {
    asm volatile("st.shared.v4.b32 [%0], {%1,%2,%3,%4};"
                 :: "r"(addr), "r"(x), "r"(y), "r"(z), "r"(w) : "memory");
}
__device__ __forceinline__ void ldsm_x4(uint32_t& r0, uint32_t& r1, uint32_t& r2,
                                        uint32_t& r3, uint32_t addr) {
    asm volatile("ldmatrix.sync.aligned.m8n8.x4.shared.b16 {%0,%1,%2,%3}, [%4];"
                 : "=r"(r0), "=r"(r1), "=r"(r2), "=r"(r3) : "r"(addr));
}
__device__ __forceinline__ void mma_f16(float c[4], const uint32_t a[4],
                                        uint32_t b0, uint32_t b1) {
    asm volatile(
        "mma.sync.aligned.m16n8k16.row.col.f32.f16.f16.f32 "
        "{%0,%1,%2,%3}, {%4,%5,%6,%7}, {%8,%9}, {%0,%1,%2,%3};\n"
        : "+f"(c[0]), "+f"(c[1]), "+f"(c[2]), "+f"(c[3])
        : "r"(a[0]), "r"(a[1]), "r"(a[2]), "r"(a[3]), "r"(b0), "r"(b1));
}
__device__ __forceinline__ uint32_t pack_h2(float a, float b) {
    __half2 h = __floats2half2_rn(a, b);
    return *reinterpret_cast<uint32_t*>(&h);
}

// ======================= K1: fp16 score GEMM, warp-specialized =======================
// CTA: 128 rows x 256 e, K=256 in 4 chunks of 64.
// 12 warps: 0-7 consumers (64x64 tile each, m16n8k16), 8-11 producers (LDG->cvt->STS).
// 3-stage smem ring: per stage A 128x64 half (16KB, SW128) + B 256x64 half (32KB).

constexpr int BM = 128;
constexpr int BK = 64;
constexpr int NCH = D / BK;      // 4
constexpr int S = 3;
constexpr int A_BYTES = BM * BK * 2;   // 16384
constexpr int B_BYTES = 256 * BK * 2;  // 32768
constexpr int STAGE = A_BYTES + B_BYTES;  // 49152
constexpr int BUF0 = 4096;
constexpr int SMEM_BYTES = BUF0 + S * STAGE;  // 151552
constexpr int NTHREADS = 384;

// smem byte map: full[s]@(s*8), empty[s]@(24+s*8); fc_b floats@[256..512),
// score_w@[512..768), esum@[768..896); stages from BUF0.

__global__ __launch_bounds__(NTHREADS, 1)
void score_kernel(const float* __restrict__ H, const float* __restrict__ fc_w,
                  const float* __restrict__ fc_b, const float* __restrict__ score_w) {
    extern __shared__ char smem[];
    float* smf = reinterpret_cast<float*>(smem);
    const uint32_t sb = smem_u32(smem);

    const int tid  = threadIdx.x;
    const int wid  = tid >> 5;
    const int lane = tid & 31;
    const int m0   = blockIdx.x * BM;

    if (tid < 256) { smf[256 + tid] = fc_b[tid]; smf[512 + tid] = score_w[tid]; }
    if (tid < 128) smf[768 + tid] = 0.0f;
    if (tid == 0) {
#pragma unroll
        for (int s = 0; s < S; ++s) {
            mbar_init(sb + s * 8, 128);        // full[s]: 128 producer arrivals
            mbar_init(sb + 24 + s * 8, 256);   // empty[s]: 256 consumer arrivals
        }
    }
    __syncthreads();

    if (wid >= 8) {
        // ---------------- producers ----------------
        const int pt = tid - 256;  // 0..127
        for (int c = 0; c < NCH; ++c) {
            const int s = c % S;
            mbar_wait(sb + 24 + s * 8, (c < S) ? 1u : 0u);  // empty[s]
            const uint32_t a_s = sb + BUF0 + s * STAGE;
            const uint32_t b_s = a_s + A_BYTES;
            const float* Ag = H + (size_t)m0 * D + c * BK;
            const float* Bg = fc_w + c * BK;
            // A: 1024 16B blocks, 8 per thread
#pragma unroll
            for (int i = 0; i < 8; ++i) {
                int blk = i * 128 + pt;
                int row = blk >> 3, kb = blk & 7;
                const float4* p = reinterpret_cast<const float4*>(Ag + (size_t)row * D + kb * 8);
                float4 v0 = p[0], v1 = p[1];
                sts128(a_s + sw128((uint32_t)(row * 128 + kb * 16)),
                       pack_h2(v0.x, v0.y), pack_h2(v0.z, v0.w),
                       pack_h2(v1.x, v1.y), pack_h2(v1.z, v1.w));
            }
            // B: 2048 16B blocks, 16 per thread
#pragma unroll
            for (int i = 0; i < 16; ++i) {
                int blk = i * 128 + pt;
                int row = blk >> 3, kb = blk & 7;
                const float4* p = reinterpret_cast<const float4*>(Bg + (size_t)row * D + kb * 8);
                float4 v0 = p[0], v1 = p[1];
                sts128(b_s + sw128((uint32_t)(row * 128 + kb * 16)),
                       pack_h2(v0.x, v0.y), pack_h2(v0.z, v0.w),
                       pack_h2(v1.x, v1.y), pack_h2(v1.z, v1.w));
            }
            mbar_arrive(sb + s * 8);  // full[s]
        }
    } else {
        // ---------------- consumers ----------------
        const int wr0 = (wid >> 2) * 64;   // row base (0/64)
        const int we0 = (wid & 3) * 64;    // e base (0/64/128/192)
        const int grp = lane >> 3;         // ldmatrix tile group
        const int rin = lane & 7;

        float acc[4][8][4];
#pragma unroll
        for (int mt = 0; mt < 4; ++mt)
#pragma unroll
            for (int nt = 0; nt < 8; ++nt)
#pragma unroll
                for (int i = 0; i < 4; ++i) acc[mt][nt][i] = 0.0f;

        for (int c = 0; c < NCH; ++c) {
            const int s = c % S;
            mbar_wait(sb + s * 8, (c < S) ? 0u : 1u);  // full[s]
            const uint32_t a_s = sb + BUF0 + s * STAGE;
            const uint32_t b_s = a_s + A_BYTES;
#pragma unroll
            for (int kk = 0; kk < 4; ++kk) {
                uint32_t a[4][4];
#pragma unroll
                for (int mt = 0; mt < 4; ++mt) {
                    int row = wr0 + mt * 16 + (grp & 1) * 8 + rin;
                    int kb  = kk * 2 + (grp >> 1);
                    ldsm_x4(a[mt][0], a[mt][1], a[mt][2], a[mt][3],
                            a_s + sw128((uint32_t)(row * 128 + kb * 16)));
                }
#pragma unroll
                for (int ntp = 0; ntp < 4; ++ntp) {
                    int row = we0 + ntp * 16 + (grp >> 1) * 8 + rin;
                    int kb  = kk * 2 + (grp & 1);
                    uint32_t b0, b1, b2, b3;
                    ldsm_x4(b0, b1, b2, b3,
                            b_s + sw128((uint32_t)(row * 128 + kb * 16)));
#pragma unroll
                    for (int mt = 0; mt < 4; ++mt) {
                        mma_f16(acc[mt][2 * ntp],     a[mt], b0, b1);
                        mma_f16(acc[mt][2 * ntp + 1], a[mt], b2, b3);
                    }
                }
            }
            mbar_arrive(sb + 24 + s * 8);  // empty[s]
        }

        // epilogue: e_row = sum_e tanh(acc + fc_b[e]) * score_w[e]
        const int g  = lane >> 2;
        const int t4 = lane & 3;
#pragma unroll
        for (int mt = 0; mt < 4; ++mt) {
            float sum0 = 0.0f, sum1 = 0.0f;
#pragma unroll
            for (int nt = 0; nt < 8; ++nt) {
                int e0 = we0 + nt * 8 + t4 * 2;
                int e1 = e0 + 1;
                float b0 = smf[256 + e0], b1 = smf[256 + e1];
                float s0 = smf[512 + e0], s1 = smf[512 + e1];
                // tanh(x) = 1 - 2/(exp(2x)+1)
                float x0 = acc[mt][nt][0] + b0, x1 = acc[mt][nt][1] + b1;
                float x2 = acc[mt][nt][2] + b0, x3 = acc[mt][nt][3] + b1;
                float th0 = 1.0f - __fdividef(2.0f, __expf(2.0f * x0) + 1.0f);
                float th1 = 1.0f - __fdividef(2.0f, __expf(2.0f * x1) + 1.0f);
                float th2 = 1.0f - __fdividef(2.0f, __expf(2.0f * x2) + 1.0f);
                float th3 = 1.0f - __fdividef(2.0f, __expf(2.0f * x3) + 1.0f);
                sum0 = fmaf(th0, s0, fmaf(th1, s1, sum0));
                sum1 = fmaf(th2, s0, fmaf(th3, s1, sum1));
            }
            sum0 += __shfl_xor_sync(0xffffffffu, sum0, 1);
            sum0 += __shfl_xor_sync(0xffffffffu, sum0, 2);
            sum1 += __shfl_xor_sync(0xffffffffu, sum1, 1);
            sum1 += __shfl_xor_sync(0xffffffffu, sum1, 2);
            if (t4 == 0) {
                atomicAdd(&smf[768 + wr0 + mt * 16 + g],     sum0);
                atomicAdd(&smf[768 + wr0 + mt * 16 + g + 8], sum1);
            }
        }
    }
    __syncthreads();
    if (tid < 128) g_e[m0 + tid] = smf[768 + tid];
}

// ======================= K2: causal softmax prefix scan =======================
// One block per channel n; 128 threads, float2/lane over D=256.
// p[t] precomputed in smem (removes g_e<->C alias serialization);
// 8-deep register prefetch of H for MLP; streaming ld/st.

constexpr int PF = 8;

__global__ __launch_bounds__(128)
void scan_kernel(const float* __restrict__ H, float* __restrict__ C) {
    const int n = blockIdx.x;
    const int tid = threadIdx.x;
    __shared__ float p_sh[T];
    __shared__ float red[4];

    // phase A: global max of e[:,n], then p[t] = exp(e-M)
    float ev[4];
    float mx = -INFINITY;
#pragma unroll
    for (int j = 0; j < 4; ++j) {
        ev[j] = g_e[(size_t)(tid * 4 + j) * N + n];
        mx = fmaxf(mx, ev[j]);
    }
#pragma unroll
    for (int o = 16; o; o >>= 1) mx = fmaxf(mx, __shfl_xor_sync(0xffffffffu, mx, o));
    if ((tid & 31) == 0) red[tid >> 5] = mx;
    __syncthreads();
    const float Mn = fmaxf(fmaxf(red[0], red[1]), fmaxf(red[2], red[3]));
#pragma unroll
    for (int j = 0; j < 4; ++j) p_sh[tid * 4 + j] = __expf(ev[j] - Mn);
    __syncthreads();

    // phase B: scan over t
    const size_t ND = (size_t)N * D;
    const float* Hp = H + (size_t)n * D + tid * 2;
    float*       Cp = C + (size_t)n * D + tid * 2;

    float2 buf[PF];
#pragma unroll
    for (int j = 0; j < PF; ++j)
        buf[j] = __ldcs(reinterpret_cast<const float2*>(Hp + (size_t)j * ND));

    float nx = 0.f, ny = 0.f, den = 0.f;
#pragma unroll 8
    for (int t = 0; t < T - PF; ++t) {
        float2 h = buf[t & (PF - 1)];
        buf[t & (PF - 1)] =
            __ldcs(reinterpret_cast<const float2*>(Hp + (size_t)(t + PF) * ND));
        float p = p_sh[t];
        den += p;
        nx = fmaf(p, h.x, nx);
        ny = fmaf(p, h.y, ny);
        float inv = __fdividef(1.0f, den);
        float2 o; o.x = nx * inv; o.y = ny * inv;
        __stcs(reinterpret_cast<float2*>(Cp + (size_t)t * ND), o);
    }
#pragma unroll
    for (int t = T - PF; t < T; ++t) {
        float2 h = buf[t & (PF - 1)];
        float p = p_sh[t];
        den += p;
        nx = fmaf(p, h.x, nx);
        ny = fmaf(p, h.y, ny);
        float inv = __fdividef(1.0f, den);
        float2 o; o.x = nx * inv; o.y = ny * inv;
        __stcs(reinterpret_cast<float2*>(Cp + (size_t)t * ND), o);
    }
}

// ======================= launch =======================
extern "C" void kernel_launch(void* const* d_in, const int* in_sizes, int n_in,
                              void* d_out, int out_size) {
    const float* H       = (const float*)d_in[0];
    const float* fc_w    = (const float*)d_in[1];
    const float* fc_b    = (const float*)d_in[2];
    const float* score_w = (const float*)d_in[3];
    float* C = (float*)d_out;

    cudaFuncSetAttribute(score_kernel, cudaFuncAttributeMaxDynamicSharedMemorySize, SMEM_BYTES);
    score_kernel<<<M_ROWS / BM, NTHREADS, SMEM_BYTES>>>(H, fc_w, fc_b, score_w);
    scan_kernel<<<N, 128>>>(H, C);
}

// round 10
// speedup vs baseline: 1.9602x; 1.1344x over previous
#include <cuda_runtime.h>
#include <cuda_fp16.h>
#include <cstdint>
#include <math.h>

constexpr int T = 512;
constexpr int N = 1024;
constexpr int D = 256;
constexpr int M_ROWS = T * N;    // 524288
constexpr int NTILES = M_ROWS / 128;  // 4096

// scratch: scores e[t,n]
__device__ float g_e[M_ROWS];

// ======================= helpers =======================
__device__ __forceinline__ uint32_t smem_u32(const void* p) {
    uint32_t a;
    asm("{ .reg .u64 t; cvta.to.shared.u64 t, %1; cvt.u32.u64 %0, t; }"
        : "=r"(a) : "l"(p));
    return a;
}
__device__ __forceinline__ uint32_t sw128(uint32_t b) { return b ^ ((b >> 3) & 0x70); }

__device__ __forceinline__ void mbar_init(uint32_t a, uint32_t cnt) {
    asm volatile("mbarrier.init.shared.b64 [%0], %1;" :: "r"(a), "r"(cnt) : "memory");
}
__device__ __forceinline__ void mbar_arrive(uint32_t a) {
    asm volatile("mbarrier.arrive.release.cta.shared::cta.b64 _, [%0];" :: "r"(a) : "memory");
}
__device__ __forceinline__ void mbar_wait(uint32_t a, uint32_t parity) {
    asm volatile(
        "{\n\t.reg .pred P;\n"
        "W_%=:\n\t"
        "mbarrier.try_wait.parity.acquire.cta.shared::cta.b64 P, [%0], %1, 0x989680;\n\t"
        "@P bra.uni DN_%=;\n\t"
        "bra.uni W_%=;\n"
        "DN_%=:\n\t}"
        :: "r"(a), "r"(parity) : "memory");
}
__device__ __forceinline__ void sts128(uint32_t addr, uint32_t x, uint32_t y,
                                       uint32_t z, uint32_t w) {
    asm volatile("st.shared.v4.b32 [%0], {%1,%2,%3,%4};"
                 :: "r"(addr), "r"(x), "r"(y), "r"(z), "r"(w) : "memory");
}
__device__ __forceinline__ void ldsm_x4(uint32_t& r0, uint32_t& r1, uint32_t& r2,
                                        uint32_t& r3, uint32_t addr) {
    asm volatile("ldmatrix.sync.aligned.m8n8.x4.shared.b16 {%0,%1,%2,%3}, [%4];"
                 : "=r"(r0), "=r"(r1), "=r"(r2), "=r"(r3) : "r"(addr));
}
__device__ __forceinline__ void mma_f16(float c[4], const uint32_t a[4],
                                        uint32_t b0, uint32_t b1) {
    asm volatile(
        "mma.sync.aligned.m16n8k16.row.col.f32.f16.f16.f32 "
        "{%0,%1,%2,%3}, {%4,%5,%6,%7}, {%8,%9}, {%0,%1,%2,%3};\n"
        : "+f"(c[0]), "+f"(c[1]), "+f"(c[2]), "+f"(c[3])
        : "r"(a[0]), "r"(a[1]), "r"(a[2]), "r"(a[3]), "r"(b0), "r"(b1));
}
__device__ __forceinline__ uint32_t pack_h2(float a, float b) {
    __half2 h = __floats2half2_rn(a, b);
    return *reinterpret_cast<uint32_t*>(&h);
}
#define CBAR() asm volatile("bar.sync 15, 256;" ::: "memory")

// ======================= K1: persistent fp16 score GEMM =======================
// Grid = #SMs. Each CTA: fc_w (fp16, 128KB) resident in smem; loops tiles
// bid, bid+G, ... Each tile = 128 rows x 256 e, K=256 in 4 chunks of 64.
// 12 warps: 0-7 consumers (64x64 each), 8-11 producers (stage A chunks only,
// 3-stage 16KB ring).

constexpr int S = 3;
constexpr int A_CH_BYTES = 128 * 64 * 2;        // 16384
constexpr int B_CH_BYTES = 256 * 64 * 2;        // 32768
constexpr int BUF0 = 4096;
constexpr int B_OFF = BUF0;                      // 4 chunks: 131072 B
constexpr int A_OFF = B_OFF + 4 * B_CH_BYTES;    // 135168
constexpr int SMEM_BYTES = A_OFF + S * A_CH_BYTES;  // 184320
constexpr int NTHREADS = 384;

// smem bytes: full[s]@ s*8, empty[s]@ 24+s*8; floats: fc_b@[256,512),
// score_w@[512,768), esum0@[768,896), esum1@[896,1024).

__global__ __launch_bounds__(NTHREADS, 1)
void score_kernel(const float* __restrict__ H, const float* __restrict__ fc_w,
                  const float* __restrict__ fc_b, const float* __restrict__ score_w) {
    extern __shared__ char smem[];
    float* smf = reinterpret_cast<float*>(smem);
    const uint32_t sb = smem_u32(smem);

    const int tid  = threadIdx.x;
    const int wid  = tid >> 5;
    const int lane = tid & 31;
    const int G    = gridDim.x;

    // ---- prologue: params, barriers, resident B (fc_w -> fp16, SW128) ----
    if (tid < 256) {
        smf[256 + tid] = fc_b[tid];
        smf[512 + tid] = score_w[tid];
        smf[768 + tid] = 0.0f;   // both esum buffers
    }
    if (tid == 0) {
#pragma unroll
        for (int s = 0; s < S; ++s) {
            mbar_init(sb + s * 8, 128);        // full[s]: producer arrivals
            mbar_init(sb + 24 + s * 8, 256);   // empty[s]: consumer arrivals
        }
    }
    for (int idx = tid; idx < 8192; idx += NTHREADS) {  // 16B blocks of B
        int c  = idx >> 11;
        int rm = idx & 2047;
        int e  = rm >> 3;
        int kb = rm & 7;
        const float4* p = reinterpret_cast<const float4*>(
            fc_w + (size_t)e * D + c * 64 + kb * 8);
        float4 v0 = p[0], v1 = p[1];
        sts128(sb + B_OFF + c * B_CH_BYTES + sw128((uint32_t)(e * 128 + kb * 16)),
               pack_h2(v0.x, v0.y), pack_h2(v0.z, v0.w),
               pack_h2(v1.x, v1.y), pack_h2(v1.z, v1.w));
    }
    __syncthreads();

    if (wid >= 8) {
        // ---------------- producers: stage A chunks ----------------
        const int pt = tid - 256;  // 0..127
        int lc = 0, s = 0, w = 0;
        for (int tile = blockIdx.x; tile < NTILES; tile += G) {
            const size_t rowbase = (size_t)tile * 128;
#pragma unroll
            for (int c = 0; c < 4; ++c) {
                if (lc >= S) mbar_wait(sb + 24 + s * 8, (uint32_t)((w - 1) & 1));
                const uint32_t a_s = sb + A_OFF + s * A_CH_BYTES;
                const float* Ag = H + rowbase * D + c * 64;
#pragma unroll
                for (int i = 0; i < 8; ++i) {
                    int blk = i * 128 + pt;
                    int row = blk >> 3, kb = blk & 7;
                    const float4* p = reinterpret_cast<const float4*>(
                        Ag + (size_t)row * D + kb * 8);
                    float4 v0 = p[0], v1 = p[1];
                    sts128(a_s + sw128((uint32_t)(row * 128 + kb * 16)),
                           pack_h2(v0.x, v0.y), pack_h2(v0.z, v0.w),
                           pack_h2(v1.x, v1.y), pack_h2(v1.z, v1.w));
                }
                mbar_arrive(sb + s * 8);
                ++lc; if (++s == S) { s = 0; w ^= 1; }
            }
        }
    } else {
        // ---------------- consumers ----------------
        const int wr0 = (wid >> 2) * 64;
        const int we0 = (wid & 3) * 64;
        const int grp = lane >> 3;
        const int rin = lane & 7;
        const int g4  = lane >> 2;
        const int t4  = lane & 3;

        int lc = 0, s = 0, w = 0, tl = 0;
        for (int tile = blockIdx.x; tile < NTILES; tile += G, ++tl) {
            float acc[4][8][4];
#pragma unroll
            for (int mt = 0; mt < 4; ++mt)
#pragma unroll
                for (int nt = 0; nt < 8; ++nt)
#pragma unroll
                    for (int i = 0; i < 4; ++i) acc[mt][nt][i] = 0.0f;

#pragma unroll
            for (int c = 0; c < 4; ++c) {
                mbar_wait(sb + s * 8, (uint32_t)(w & 1));
                const uint32_t a_s = sb + A_OFF + s * A_CH_BYTES;
                const uint32_t b_s = sb + B_OFF + c * B_CH_BYTES;
#pragma unroll
                for (int kk = 0; kk < 4; ++kk) {
                    uint32_t a[4][4];
#pragma unroll
                    for (int mt = 0; mt < 4; ++mt) {
                        int row = wr0 + mt * 16 + (grp & 1) * 8 + rin;
                        int kb  = kk * 2 + (grp >> 1);
                        ldsm_x4(a[mt][0], a[mt][1], a[mt][2], a[mt][3],
                                a_s + sw128((uint32_t)(row * 128 + kb * 16)));
                    }
#pragma unroll
                    for (int ntp = 0; ntp < 4; ++ntp) {
                        int row = we0 + ntp * 16 + (grp >> 1) * 8 + rin;
                        int kb  = kk * 2 + (grp & 1);
                        uint32_t b0, b1, b2, b3;
                        ldsm_x4(b0, b1, b2, b3,
                                b_s + sw128((uint32_t)(row * 128 + kb * 16)));
#pragma unroll
                        for (int mt = 0; mt < 4; ++mt) {
                            mma_f16(acc[mt][2 * ntp],     a[mt], b0, b1);
                            mma_f16(acc[mt][2 * ntp + 1], a[mt], b2, b3);
                        }
                    }
                }
                mbar_arrive(sb + 24 + s * 8);
                ++lc; if (++s == S) { s = 0; w ^= 1; }
            }

            // ---- epilogue: e_row = sum_e tanh(acc + fc_b[e]) * score_w[e] ----
            float* es = smf + 768 + (tl & 1) * 128;
#pragma unroll
            for (int mt = 0; mt < 4; ++mt) {
                float sum0 = 0.0f, sum1 = 0.0f;
#pragma unroll
                for (int nt = 0; nt < 8; ++nt) {
                    int e0 = we0 + nt * 8 + t4 * 2;
                    int e1 = e0 + 1;
                    float b0 = smf[256 + e0], b1 = smf[256 + e1];
                    float s0 = smf[512 + e0], s1 = smf[512 + e1];
                    float x0 = acc[mt][nt][0] + b0, x1 = acc[mt][nt][1] + b1;
                    float x2 = acc[mt][nt][2] + b0, x3 = acc[mt][nt][3] + b1;
                    float th0 = 1.0f - __fdividef(2.0f, __expf(2.0f * x0) + 1.0f);
                    float th1 = 1.0f - __fdividef(2.0f, __expf(2.0f * x1) + 1.0f);
                    float th2 = 1.0f - __fdividef(2.0f, __expf(2.0f * x2) + 1.0f);
                    float th3 = 1.0f - __fdividef(2.0f, __expf(2.0f * x3) + 1.0f);
                    sum0 = fmaf(th0, s0, fmaf(th1, s1, sum0));
                    sum1 = fmaf(th2, s0, fmaf(th3, s1, sum1));
                }
                sum0 += __shfl_xor_sync(0xffffffffu, sum0, 1);
                sum0 += __shfl_xor_sync(0xffffffffu, sum0, 2);
                sum1 += __shfl_xor_sync(0xffffffffu, sum1, 1);
                sum1 += __shfl_xor_sync(0xffffffffu, sum1, 2);
                if (t4 == 0) {
                    atomicAdd(&es[wr0 + mt * 16 + g4],     sum0);
                    atomicAdd(&es[wr0 + mt * 16 + g4 + 8], sum1);
                }
            }
            CBAR();
            if (tid < 128) {
                g_e[(size_t)tile * 128 + tid] = es[tid];
                es[tid] = 0.0f;
            }
            CBAR();
        }
    }
}

// ======================= K2: causal softmax prefix scan =======================
// One block per channel n; 128 threads, float2/lane over D=256; p[t] in smem;
// 8-deep register prefetch; streaming ld/st. (Measured 80.3% DRAM — at floor.)

constexpr int PF = 8;

__global__ __launch_bounds__(128)
void scan_kernel(const float* __restrict__ H, float* __restrict__ C) {
    const int n = blockIdx.x;
    const int tid = threadIdx.x;
    __shared__ float p_sh[T];
    __shared__ float red[4];

    float ev[4];
    float mx = -INFINITY;
#pragma unroll
    for (int j = 0; j < 4; ++j) {
        ev[j] = g_e[(size_t)(tid * 4 + j) * N + n];
        mx = fmaxf(mx, ev[j]);
    }
#pragma unroll
    for (int o = 16; o; o >>= 1) mx = fmaxf(mx, __shfl_xor_sync(0xffffffffu, mx, o));
    if ((tid & 31) == 0) red[tid >> 5] = mx;
    __syncthreads();
    const float Mn = fmaxf(fmaxf(red[0], red[1]), fmaxf(red[2], red[3]));
#pragma unroll
    for (int j = 0; j < 4; ++j) p_sh[tid * 4 + j] = __expf(ev[j] - Mn);
    __syncthreads();

    const size_t ND = (size_t)N * D;
    const float* Hp = H + (size_t)n * D + tid * 2;
    float*       Cp = C + (size_t)n * D + tid * 2;

    float2 buf[PF];
#pragma unroll
    for (int j = 0; j < PF; ++j)
        buf[j] = __ldcs(reinterpret_cast<const float2*>(Hp + (size_t)j * ND));

    float nx = 0.f, ny = 0.f, den = 0.f;
#pragma unroll 8
    for (int t = 0; t < T - PF; ++t) {
        float2 h = buf[t & (PF - 1)];
        buf[t & (PF - 1)] =
            __ldcs(reinterpret_cast<const float2*>(Hp + (size_t)(t + PF) * ND));
        float p = p_sh[t];
        den += p;
        nx = fmaf(p, h.x, nx);
        ny = fmaf(p, h.y, ny);
        float inv = __fdividef(1.0f, den);
        float2 o; o.x = nx * inv; o.y = ny * inv;
        __stcs(reinterpret_cast<float2*>(Cp + (size_t)t * ND), o);
    }
#pragma unroll
    for (int t = T - PF; t < T; ++t) {
        float2 h = buf[t & (PF - 1)];
        float p = p_sh[t];
        den += p;
        nx = fmaf(p, h.x, nx);
        ny = fmaf(p, h.y, ny);
        float inv = __fdividef(1.0f, den);
        float2 o; o.x = nx * inv; o.y = ny * inv;
        __stcs(reinterpret_cast<float2*>(Cp + (size_t)t * ND), o);
    }
}

// ======================= launch =======================
extern "C" void kernel_launch(void* const* d_in, const int* in_sizes, int n_in,
                              void* d_out, int out_size) {
    const float* H       = (const float*)d_in[0];
    const float* fc_w    = (const float*)d_in[1];
    const float* fc_b    = (const float*)d_in[2];
    const float* score_w = (const float*)d_in[3];
    float* C = (float*)d_out;

    int G = 148;
    cudaDeviceGetAttribute(&G, cudaDevAttrMultiProcessorCount, 0);

    cudaFuncSetAttribute(score_kernel, cudaFuncAttributeMaxDynamicSharedMemorySize, SMEM_BYTES);
    score_kernel<<<G, NTHREADS, SMEM_BYTES>>>(H, fc_w, fc_b, score_w);
    scan_kernel<<<N, 128>>>(H, C);
}

// round 11
// speedup vs baseline: 2.1980x; 1.1213x over previous
#include <cuda_runtime.h>
#include <cuda_fp16.h>
#include <cstdint>
#include <math.h>

constexpr int T = 512;
constexpr int N = 1024;
constexpr int D = 256;
constexpr int M_ROWS = T * N;    // 524288
constexpr int NTILES = M_ROWS / 128;  // 4096

// scratch: scores e[t,n]
__device__ float g_e[M_ROWS];

// ======================= helpers =======================
__device__ __forceinline__ uint32_t smem_u32(const void* p) {
    uint32_t a;
    asm("{ .reg .u64 t; cvta.to.shared.u64 t, %1; cvt.u32.u64 %0, t; }"
        : "=r"(a) : "l"(p));
    return a;
}
__device__ __forceinline__ uint32_t sw128(uint32_t b) { return b ^ ((b >> 3) & 0x70); }

__device__ __forceinline__ void mbar_init(uint32_t a, uint32_t cnt) {
    asm volatile("mbarrier.init.shared.b64 [%0], %1;" :: "r"(a), "r"(cnt) : "memory");
}
__device__ __forceinline__ void mbar_arrive(uint32_t a) {
    asm volatile("mbarrier.arrive.release.cta.shared::cta.b64 _, [%0];" :: "r"(a) : "memory");
}
__device__ __forceinline__ void mbar_wait(uint32_t a, uint32_t parity) {
    asm volatile(
        "{\n\t.reg .pred P;\n"
        "W_%=:\n\t"
        "mbarrier.try_wait.parity.acquire.cta.shared::cta.b64 P, [%0], %1, 0x989680;\n\t"
        "@P bra.uni DN_%=;\n\t"
        "bra.uni W_%=;\n"
        "DN_%=:\n\t}"
        :: "r"(a), "r"(parity) : "memory");
}
__device__ __forceinline__ void sts128(uint32_t addr, uint32_t x, uint32_t y,
                                       uint32_t z, uint32_t w) {
    asm volatile("st.shared.v4.b32 [%0], {%1,%2,%3,%4};"
                 :: "r"(addr), "r"(x), "r"(y), "r"(z), "r"(w) : "memory");
}
__device__ __forceinline__ void ldsm_x4(uint32_t& r0, uint32_t& r1, uint32_t& r2,
                                        uint32_t& r3, uint32_t addr) {
    asm volatile("ldmatrix.sync.aligned.m8n8.x4.shared.b16 {%0,%1,%2,%3}, [%4];"
                 : "=r"(r0), "=r"(r1), "=r"(r2), "=r"(r3) : "r"(addr));
}
__device__ __forceinline__ void mma_f16(float c[4], const uint32_t a[4],
                                        uint32_t b0, uint32_t b1) {
    asm volatile(
        "mma.sync.aligned.m16n8k16.row.col.f32.f16.f16.f32 "
        "{%0,%1,%2,%3}, {%4,%5,%6,%7}, {%8,%9}, {%0,%1,%2,%3};\n"
        : "+f"(c[0]), "+f"(c[1]), "+f"(c[2]), "+f"(c[3])
        : "r"(a[0]), "r"(a[1]), "r"(a[2]), "r"(a[3]), "r"(b0), "r"(b1));
}
__device__ __forceinline__ uint32_t pack_h2(float a, float b) {
    __half2 h = __floats2half2_rn(a, b);
    return *reinterpret_cast<uint32_t*>(&h);
}
__device__ __forceinline__ float tanh_fast(float x) {
    float y;
    asm("tanh.approx.f32 %0, %1;" : "=f"(y) : "f"(x));
    return y;
}
#define CBAR() asm volatile("bar.sync 15, 256;" ::: "memory")

// ======================= K1: persistent fp16 score GEMM =======================
// Grid = #SMs. Each CTA: fc_w (fp16, 128KB) resident in smem; loops tiles
// bid, bid+G, ... Each tile = 128 rows x 256 e, K=256 in 4 chunks of 64.
// 12 warps: 0-7 consumers (64x64 each), 8-11 producers (stage A chunks only,
// 3-stage 16KB ring).

constexpr int S = 3;
constexpr int A_CH_BYTES = 128 * 64 * 2;        // 16384
constexpr int B_CH_BYTES = 256 * 64 * 2;        // 32768
constexpr int BUF0 = 4096;
constexpr int B_OFF = BUF0;                      // 4 chunks: 131072 B
constexpr int A_OFF = B_OFF + 4 * B_CH_BYTES;    // 135168
constexpr int SMEM_BYTES = A_OFF + S * A_CH_BYTES;  // 184320
constexpr int NTHREADS = 384;

// smem bytes: full[s]@ s*8, empty[s]@ 24+s*8; floats: fc_b@[256,512),
// score_w@[512,768), esum0@[768,896), esum1@[896,1024).

__global__ __launch_bounds__(NTHREADS, 1)
void score_kernel(const float* __restrict__ H, const float* __restrict__ fc_w,
                  const float* __restrict__ fc_b, const float* __restrict__ score_w) {
    extern __shared__ char smem[];
    float* smf = reinterpret_cast<float*>(smem);
    const uint32_t sb = smem_u32(smem);

    const int tid  = threadIdx.x;
    const int wid  = tid >> 5;
    const int lane = tid & 31;
    const int G    = gridDim.x;

    // ---- prologue: params, barriers, resident B (fc_w -> fp16, SW128) ----
    if (tid < 256) {
        smf[256 + tid] = fc_b[tid];
        smf[512 + tid] = score_w[tid];
        smf[768 + tid] = 0.0f;   // both esum buffers
    }
    if (tid == 0) {
#pragma unroll
        for (int s = 0; s < S; ++s) {
            mbar_init(sb + s * 8, 128);        // full[s]: producer arrivals
            mbar_init(sb + 24 + s * 8, 256);   // empty[s]: consumer arrivals
        }
    }
    for (int idx = tid; idx < 8192; idx += NTHREADS) {  // 16B blocks of B
        int c  = idx >> 11;
        int rm = idx & 2047;
        int e  = rm >> 3;
        int kb = rm & 7;
        const float4* p = reinterpret_cast<const float4*>(
            fc_w + (size_t)e * D + c * 64 + kb * 8);
        float4 v0 = p[0], v1 = p[1];
        sts128(sb + B_OFF + c * B_CH_BYTES + sw128((uint32_t)(e * 128 + kb * 16)),
               pack_h2(v0.x, v0.y), pack_h2(v0.z, v0.w),
               pack_h2(v1.x, v1.y), pack_h2(v1.z, v1.w));
    }
    __syncthreads();

    if (wid >= 8) {
        // ---------------- producers: stage A chunks ----------------
        const int pt = tid - 256;  // 0..127
        int lc = 0, s = 0, w = 0;
        for (int tile = blockIdx.x; tile < NTILES; tile += G) {
            const size_t rowbase = (size_t)tile * 128;
#pragma unroll
            for (int c = 0; c < 4; ++c) {
                if (lc >= S) mbar_wait(sb + 24 + s * 8, (uint32_t)((w - 1) & 1));
                const uint32_t a_s = sb + A_OFF + s * A_CH_BYTES;
                const float* Ag = H + rowbase * D + c * 64;
#pragma unroll
                for (int i = 0; i < 8; ++i) {
                    int blk = i * 128 + pt;
                    int row = blk >> 3, kb = blk & 7;
                    const float4* p = reinterpret_cast<const float4*>(
                        Ag + (size_t)row * D + kb * 8);
                    float4 v0 = p[0], v1 = p[1];
                    sts128(a_s + sw128((uint32_t)(row * 128 + kb * 16)),
                           pack_h2(v0.x, v0.y), pack_h2(v0.z, v0.w),
                           pack_h2(v1.x, v1.y), pack_h2(v1.z, v1.w));
                }
                mbar_arrive(sb + s * 8);
                ++lc; if (++s == S) { s = 0; w ^= 1; }
            }
        }
    } else {
        // ---------------- consumers ----------------
        const int wr0 = (wid >> 2) * 64;
        const int we0 = (wid & 3) * 64;
        const int grp = lane >> 3;
        const int rin = lane & 7;
        const int g4  = lane >> 2;
        const int t4  = lane & 3;

        int lc = 0, s = 0, w = 0, tl = 0;
        for (int tile = blockIdx.x; tile < NTILES; tile += G, ++tl) {
            float acc[4][8][4];
#pragma unroll
            for (int mt = 0; mt < 4; ++mt)
#pragma unroll
                for (int nt = 0; nt < 8; ++nt)
#pragma unroll
                    for (int i = 0; i < 4; ++i) acc[mt][nt][i] = 0.0f;

#pragma unroll
            for (int c = 0; c < 4; ++c) {
                mbar_wait(sb + s * 8, (uint32_t)(w & 1));
                const uint32_t a_s = sb + A_OFF + s * A_CH_BYTES;
                const uint32_t b_s = sb + B_OFF + c * B_CH_BYTES;
#pragma unroll
                for (int kk = 0; kk < 4; ++kk) {
                    uint32_t a[4][4];
#pragma unroll
                    for (int mt = 0; mt < 4; ++mt) {
                        int row = wr0 + mt * 16 + (grp & 1) * 8 + rin;
                        int kb  = kk * 2 + (grp >> 1);
                        ldsm_x4(a[mt][0], a[mt][1], a[mt][2], a[mt][3],
                                a_s + sw128((uint32_t)(row * 128 + kb * 16)));
                    }
#pragma unroll
                    for (int ntp = 0; ntp < 4; ++ntp) {
                        int row = we0 + ntp * 16 + (grp >> 1) * 8 + rin;
                        int kb  = kk * 2 + (grp & 1);
                        uint32_t b0, b1, b2, b3;
                        ldsm_x4(b0, b1, b2, b3,
                                b_s + sw128((uint32_t)(row * 128 + kb * 16)));
#pragma unroll
                        for (int mt = 0; mt < 4; ++mt) {
                            mma_f16(acc[mt][2 * ntp],     a[mt], b0, b1);
                            mma_f16(acc[mt][2 * ntp + 1], a[mt], b2, b3);
                        }
                    }
                }
                mbar_arrive(sb + 24 + s * 8);
                ++lc; if (++s == S) { s = 0; w ^= 1; }
            }

            // ---- epilogue: e_row = sum_e tanh(acc + fc_b[e]) * score_w[e] ----
            // nt-outer: fc_b/score_w loaded once per nt; MUFU.TANH (1 op/val).
            float* es = smf + 768 + (tl & 1) * 128;
            float sum0[4] = {0.f, 0.f, 0.f, 0.f};
            float sum1[4] = {0.f, 0.f, 0.f, 0.f};
#pragma unroll
            for (int nt = 0; nt < 8; ++nt) {
                int e0 = we0 + nt * 8 + t4 * 2;
                int e1 = e0 + 1;
                float b0 = smf[256 + e0], b1 = smf[256 + e1];
                float s0 = smf[512 + e0], s1 = smf[512 + e1];
#pragma unroll
                for (int mt = 0; mt < 4; ++mt) {
                    float th0 = tanh_fast(acc[mt][nt][0] + b0);
                    float th1 = tanh_fast(acc[mt][nt][1] + b1);
                    float th2 = tanh_fast(acc[mt][nt][2] + b0);
                    float th3 = tanh_fast(acc[mt][nt][3] + b1);
                    sum0[mt] = fmaf(th0, s0, fmaf(th1, s1, sum0[mt]));
                    sum1[mt] = fmaf(th2, s0, fmaf(th3, s1, sum1[mt]));
                }
            }
#pragma unroll
            for (int mt = 0; mt < 4; ++mt) {
                float a0 = sum0[mt], a1 = sum1[mt];
                a0 += __shfl_xor_sync(0xffffffffu, a0, 1);
                a0 += __shfl_xor_sync(0xffffffffu, a0, 2);
                a1 += __shfl_xor_sync(0xffffffffu, a1, 1);
                a1 += __shfl_xor_sync(0xffffffffu, a1, 2);
                if (t4 == 0) {
                    atomicAdd(&es[wr0 + mt * 16 + g4],     a0);
                    atomicAdd(&es[wr0 + mt * 16 + g4 + 8], a1);
                }
            }
            CBAR();
            if (tid < 128) {
                g_e[(size_t)tile * 128 + tid] = es[tid];
                es[tid] = 0.0f;
            }
            CBAR();
        }
    }
}

// ======================= K2: causal softmax prefix scan =======================
// One block per channel n; 128 threads, float2/lane over D=256; p[t] in smem;
// 8-deep register prefetch; streaming ld/st. (Measured 80.4% DRAM — at floor.)

constexpr int PF = 8;

__global__ __launch_bounds__(128)
void scan_kernel(const float* __restrict__ H, float* __restrict__ C) {
    const int n = blockIdx.x;
    const int tid = threadIdx.x;
    __shared__ float p_sh[T];
    __shared__ float red[4];

    float ev[4];
    float mx = -INFINITY;
#pragma unroll
    for (int j = 0; j < 4; ++j) {
        ev[j] = g_e[(size_t)(tid * 4 + j) * N + n];
        mx = fmaxf(mx, ev[j]);
    }
#pragma unroll
    for (int o = 16; o; o >>= 1) mx = fmaxf(mx, __shfl_xor_sync(0xffffffffu, mx, o));
    if ((tid & 31) == 0) red[tid >> 5] = mx;
    __syncthreads();
    const float Mn = fmaxf(fmaxf(red[0], red[1]), fmaxf(red[2], red[3]));
#pragma unroll
    for (int j = 0; j < 4; ++j) p_sh[tid * 4 + j] = __expf(ev[j] - Mn);
    __syncthreads();

    const size_t ND = (size_t)N * D;
    const float* Hp = H + (size_t)n * D + tid * 2;
    float*       Cp = C + (size_t)n * D + tid * 2;

    float2 buf[PF];
#pragma unroll
    for (int j = 0; j < PF; ++j)
        buf[j] = __ldcs(reinterpret_cast<const float2*>(Hp + (size_t)j * ND));

    float nx = 0.f, ny = 0.f, den = 0.f;
#pragma unroll 8
    for (int t = 0; t < T - PF; ++t) {
        float2 h = buf[t & (PF - 1)];
        buf[t & (PF - 1)] =
            __ldcs(reinterpret_cast<const float2*>(Hp + (size_t)(t + PF) * ND));
        float p = p_sh[t];
        den += p;
        nx = fmaf(p, h.x, nx);
        ny = fmaf(p, h.y, ny);
        float inv = __fdividef(1.0f, den);
        float2 o; o.x = nx * inv; o.y = ny * inv;
        __stcs(reinterpret_cast<float2*>(Cp + (size_t)t * ND), o);
    }
#pragma unroll
    for (int t = T - PF; t < T; ++t) {
        float2 h = buf[t & (PF - 1)];
        float p = p_sh[t];
        den += p;
        nx = fmaf(p, h.x, nx);
        ny = fmaf(p, h.y, ny);
        float inv = __fdividef(1.0f, den);
        float2 o; o.x = nx * inv; o.y = ny * inv;
        __stcs(reinterpret_cast<float2*>(Cp + (size_t)t * ND), o);
    }
}

// ======================= launch =======================
extern "C" void kernel_launch(void* const* d_in, const int* in_sizes, int n_in,
                              void* d_out, int out_size) {
    const float* H       = (const float*)d_in[0];
    const float* fc_w    = (const float*)d_in[1];
    const float* fc_b    = (const float*)d_in[2];
    const float* score_w = (const float*)d_in[3];
    float* C = (float*)d_out;

    int G = 148;
    cudaDeviceGetAttribute(&G, cudaDevAttrMultiProcessorCount, 0);

    cudaFuncSetAttribute(score_kernel, cudaFuncAttributeMaxDynamicSharedMemorySize, SMEM_BYTES);
    score_kernel<<<G, NTHREADS, SMEM_BYTES>>>(H, fc_w, fc_b, score_w);
    scan_kernel<<<N, 128>>>(H, C);
}